// round 2
// baseline (speedup 1.0000x reference)
#include <cuda_runtime.h>

// ---------------- problem constants ----------------
constexpr int Bz = 4, Cn = 128, Hh = 128, Wd = 128;
constexpr int HW = Hh * Wd;       // 16384
constexpr int P  = Bz * HW;       // 65536 pixels
constexpr int NCH = 128, CL = 128; // scan: 128 chunks of 128 steps (L = 16384)

// ---------------- scratch (device globals; no allocation allowed) ----------------
__device__ float g_xin [P * Cn];
__device__ float g_xc  [P * Cn];
__device__ float g_off [P * 16];
__device__ float g_xd  [P * Cn];
__device__ float g_xdbl[P * 10];
__device__ float g_As  [Bz * NCH * Cn];
__device__ float g_Bs  [Bz * NCH * Cn];
__device__ float g_hin [Bz * NCH * Cn];
__device__ float g_y   [P * Cn];

// =====================================================================
// K1: in_proj 1x1 GEMM.  x (B,C,HW) channel-major -> xin channels-last (p,c)
// tile: 64 pixels x 128 outputs, 256 threads, 4x8 microtile
// =====================================================================
__global__ void k_in_proj(const float* __restrict__ x, const float* __restrict__ w) {
    extern __shared__ float sm[];
    float* Ws = sm;               // [128][132]  Ws[c*132+o] = w[o][c]
    float* Xs = sm + 128 * 132;   // [128][68]   Xs[c*68+j]  = x[c][pix j]
    const int t  = threadIdx.x;
    const int p0 = blockIdx.x * 64;
    const int b  = p0 / HW, hw0 = p0 % HW;

    for (int i = t; i < 128 * 128; i += 256) {
        int o = i >> 7, c = i & 127;
        Ws[c * 132 + o] = w[i];
    }
    for (int i = t; i < 128 * 64; i += 256) {
        int c = i >> 6, j = i & 63;
        Xs[c * 68 + j] = x[(b * Cn + c) * HW + hw0 + j];
    }
    __syncthreads();

    const int tx = t & 15, ty = t >> 4;   // tx: pixel group (4), ty: output group (8)
    float acc[4][8];
#pragma unroll
    for (int i = 0; i < 4; i++)
#pragma unroll
        for (int j = 0; j < 8; j++) acc[i][j] = 0.f;

#pragma unroll 4
    for (int c = 0; c < 128; ++c) {
        float4 xa = *(const float4*)&Xs[c * 68 + tx * 4];
        float4 w0 = *(const float4*)&Ws[c * 132 + ty * 8];
        float4 w1 = *(const float4*)&Ws[c * 132 + ty * 8 + 4];
        float xv[4] = {xa.x, xa.y, xa.z, xa.w};
        float wv[8] = {w0.x, w0.y, w0.z, w0.w, w1.x, w1.y, w1.z, w1.w};
#pragma unroll
        for (int i = 0; i < 4; i++)
#pragma unroll
            for (int j = 0; j < 8; j++) acc[i][j] += xv[i] * wv[j];
    }
#pragma unroll
    for (int i = 0; i < 4; i++) {
        float* dst = &g_xin[(p0 + tx * 4 + i) * Cn + ty * 8];
        *(float4*)(dst)     = make_float4(acc[i][0], acc[i][1], acc[i][2], acc[i][3]);
        *(float4*)(dst + 4) = make_float4(acc[i][4], acc[i][5], acc[i][6], acc[i][7]);
    }
}

// =====================================================================
// K2: depthwise 3x3 conv + bias + SiLU  (channels-last, zero-pad SAME)
// =====================================================================
__global__ void k_dwsilu(const float* __restrict__ w, const float* __restrict__ bias) {
    const int t = threadIdx.x;
    const int p = blockIdx.x * 2 + (t >> 7);
    const int c = t & 127;
    const int b = p / HW, hw = p % HW, yy = hw / Wd, xx = hw % Wd;
    float wr[9];
#pragma unroll
    for (int k = 0; k < 9; k++) wr[k] = w[c * 9 + k];
    float acc = bias[c];
#pragma unroll
    for (int ky = 0; ky < 3; ky++) {
        int yv = yy + ky - 1;
        if ((unsigned)yv >= (unsigned)Hh) continue;
#pragma unroll
        for (int kx = 0; kx < 3; kx++) {
            int xv = xx + kx - 1;
            if ((unsigned)xv >= (unsigned)Wd) continue;
            acc += wr[ky * 3 + kx] * g_xin[(b * HW + yv * Wd + xv) * Cn + c];
        }
    }
    g_xc[p * Cn + c] = acc / (1.f + __expf(-acc));
}

// =====================================================================
// K3: dwconv(dw_w)+bias -> LN(channels) -> exact GELU -> offsets (16 per pixel)
// one block per pixel, 128 threads (= channels)
// =====================================================================
__global__ void k_dw2_off(const float* __restrict__ w, const float* __restrict__ bias,
                          const float* __restrict__ lng, const float* __restrict__ lnb,
                          const float* __restrict__ offw, const float* __restrict__ offb) {
    __shared__ float s[128];
    __shared__ float red[8];
    __shared__ float smr[2];
    const int c = threadIdx.x;
    const int p = blockIdx.x;
    const int b = p / HW, hw = p % HW, yy = hw / Wd, xx = hw % Wd;

    float acc = bias[c];
#pragma unroll
    for (int ky = 0; ky < 3; ky++) {
        int yv = yy + ky - 1;
        if ((unsigned)yv >= (unsigned)Hh) continue;
#pragma unroll
        for (int kx = 0; kx < 3; kx++) {
            int xv = xx + kx - 1;
            if ((unsigned)xv >= (unsigned)Wd) continue;
            acc += w[c * 9 + ky * 3 + kx] * g_xc[(b * HW + yv * Wd + xv) * Cn + c];
        }
    }
    const float v = acc;
    float s1 = v, s2 = v * v;
#pragma unroll
    for (int o = 16; o; o >>= 1) {
        s1 += __shfl_down_sync(0xffffffffu, s1, o);
        s2 += __shfl_down_sync(0xffffffffu, s2, o);
    }
    const int wid = c >> 5;
    if ((c & 31) == 0) { red[wid] = s1; red[4 + wid] = s2; }
    __syncthreads();
    if (c == 0) {
        float a  = red[0] + red[1] + red[2] + red[3];
        float bq = red[4] + red[5] + red[6] + red[7];
        float m  = a * (1.f / 128.f);
        float var = bq * (1.f / 128.f) - m * m;
        smr[0] = m; smr[1] = rsqrtf(var + 1e-6f);
    }
    __syncthreads();
    float xn = (v - smr[0]) * smr[1] * lng[c] + lnb[c];
    s[c] = 0.5f * xn * (1.f + erff(xn * 0.70710678118654752f));
    __syncthreads();
    // offset matvec: 16 outputs, 8 lanes per output
    const int o = c >> 3, seg = c & 7;
    float a2 = 0.f;
#pragma unroll
    for (int k = 0; k < 16; k++) a2 += s[seg * 16 + k] * offw[o * 128 + seg * 16 + k];
#pragma unroll
    for (int d = 4; d; d >>= 1) a2 += __shfl_down_sync(0xffffffffu, a2, d, 8);
    if (seg == 0) g_off[p * 16 + o] = a2 + offb[o];
}

// =====================================================================
// K4: DCNv3 (k=1, mask=1) bilinear sample with zero padding, per-group offset
// =====================================================================
__global__ void k_dcn() {
    __shared__ float so[16];
    const int d = threadIdx.x;
    const int p = blockIdx.x;
    if (d < 16) so[d] = g_off[p * 16 + d];
    __syncthreads();
    const int b = p / HW, hw = p % HW, yy = hw / Wd, xx = hw % Wd;
    const int g = d >> 4;
    const float px = (float)xx + so[g * 2];
    const float py = (float)yy + so[g * 2 + 1];
    const float x0 = floorf(px), y0 = floorf(py);
    const float wx = px - x0, wy = py - y0;
    float acc = 0.f;
#pragma unroll
    for (int dy = 0; dy < 2; dy++) {
#pragma unroll
        for (int dx = 0; dx < 2; dx++) {
            float yif = y0 + (float)dy, xif = x0 + (float)dx;
            float wgt = (dy ? wy : 1.f - wy) * (dx ? wx : 1.f - wx);
            bool valid = (yif >= 0.f) && (yif < (float)Hh) && (xif >= 0.f) && (xif < (float)Wd);
            int yi = (int)fminf(fmaxf(yif, 0.f), (float)(Hh - 1));
            int xi = (int)fminf(fmaxf(xif, 0.f), (float)(Wd - 1));
            float v = g_xc[(b * HW + yi * Wd + xi) * Cn + d];
            acc += v * (valid ? wgt : 0.f);
        }
    }
    g_xd[p * Cn + d] = acc;
}

// =====================================================================
// K5: x_dbl = x_proj_w (10x128) @ xd   -> (p,10)
// 32 pixels per block, 320 threads (pixel,row)
// =====================================================================
__global__ void k_xdbl(const float* __restrict__ xpw) {
    __shared__ float s[32 * 128];
    __shared__ float sw[10 * 128];
    const int t = threadIdx.x;
    const int p0 = blockIdx.x * 32;
    for (int i = t; i < 32 * 128; i += 320) s[i] = g_xd[p0 * 128 + i];
    for (int i = t; i < 1280; i += 320) sw[i] = xpw[i];
    __syncthreads();
    const int pl = t / 10, r = t - pl * 10;
    float acc = 0.f;
#pragma unroll 4
    for (int c = 0; c < 128; c++) acc += s[pl * 128 + c] * sw[r * 128 + c];
    g_xdbl[(p0 + pl) * 10 + r] = acc;
}

__device__ __forceinline__ float softplusf(float x) {
    return fmaxf(x, 0.f) + log1pf(__expf(-fabsf(x)));
}

// =====================================================================
// K6: scan pass 1 — per-chunk summaries (A = prod a, B = local h)
// grid (NCH, B), block 128 (one thread per channel d)
// =====================================================================
__global__ void k_scan1(const float* __restrict__ dtw, const float* __restrict__ dtb,
                        const float* __restrict__ alog) {
    const int d = threadIdx.x;
    const int chunk = blockIdx.x, b = blockIdx.y;
    float wreg[8];
#pragma unroll
    for (int r = 0; r < 8; r++) wreg[r] = dtw[d * 8 + r];
    const float bd = dtb[d];
    const float negA = -__expf(alog[d]);
    float Ar = 1.f, h = 0.f;
    const int base = b * HW + chunk * CL;
    for (int i = 0; i < CL; i++) {
        const int p = base + i;
        const float* xb = &g_xdbl[p * 10];
        float dtr = bd;
#pragma unroll
        for (int r = 0; r < 8; r++) dtr += wreg[r] * xb[r];
        float delta = softplusf(dtr);
        float a = __expf(delta * negA);
        float bx = delta * xb[8] * g_xd[p * 128 + d];
        Ar *= a;
        h = a * h + bx;
    }
    const int idx = (b * NCH + chunk) * 128 + d;
    g_As[idx] = Ar;
    g_Bs[idx] = h;
}

// K7: scan pass 2 — sequential combine of chunk summaries per (b,d)
__global__ void k_scan2() {
    const int b = blockIdx.x, d = threadIdx.x;
    float h = 0.f;
    for (int ch = 0; ch < NCH; ch++) {
        const int idx = (b * NCH + ch) * 128 + d;
        g_hin[idx] = h;
        h = g_As[idx] * h + g_Bs[idx];
    }
}

// K8: scan pass 3 — recompute with known h_in, emit y = h*C + Ds*x (channels-last)
__global__ void k_scan3(const float* __restrict__ dtw, const float* __restrict__ dtb,
                        const float* __restrict__ alog, const float* __restrict__ Ds) {
    const int d = threadIdx.x;
    const int chunk = blockIdx.x, b = blockIdx.y;
    float wreg[8];
#pragma unroll
    for (int r = 0; r < 8; r++) wreg[r] = dtw[d * 8 + r];
    const float bd = dtb[d];
    const float negA = -__expf(alog[d]);
    const float Dd = Ds[d];
    float h = g_hin[(b * NCH + chunk) * 128 + d];
    const int base = b * HW + chunk * CL;
    for (int i = 0; i < CL; i++) {
        const int p = base + i;
        const float* xb = &g_xdbl[p * 10];
        float dtr = bd;
#pragma unroll
        for (int r = 0; r < 8; r++) dtr += wreg[r] * xb[r];
        float delta = softplusf(dtr);
        float a = __expf(delta * negA);
        float xv = g_xd[p * 128 + d];
        float bx = delta * xb[8] * xv;
        h = a * h + bx;
        g_y[p * 128 + d] = h * xb[9] + Dd * xv;
    }
}

// =====================================================================
// K9: out LayerNorm (fused into tile load) + out_proj GEMM
// y channels-last -> out channels-first (B,C,H,W)
// =====================================================================
__global__ void k_out_proj(const float* __restrict__ w, const float* __restrict__ lng,
                           const float* __restrict__ lnb, float* __restrict__ out) {
    extern __shared__ float sm[];
    float* Ws    = sm;                 // 128*132
    float* Ys    = sm + 128 * 132;     // 128*68
    float* sred  = Ys + 128 * 68;      // 256
    float* s2red = sred + 256;         // 256
    float* smean = s2red + 256;        // 64
    float* srstd = smean + 64;         // 64
    const int t  = threadIdx.x;
    const int p0 = blockIdx.x * 64;
    const int b  = p0 / HW, hw0 = p0 % HW;

    for (int i = t; i < 128 * 128; i += 256) {
        int o = i >> 7, c = i & 127;
        Ws[c * 132 + o] = w[i];
    }
    for (int i = t; i < 128 * 64; i += 256) {
        int c = i & 127, j = i >> 7;
        Ys[c * 68 + j] = g_y[(p0 + j) * Cn + c];
    }
    __syncthreads();

    // fused LN over channels, per pixel j
    const int j = t & 63, part = t >> 6;
    {
        float s = 0.f, s2 = 0.f;
        for (int c = part * 32; c < part * 32 + 32; c++) {
            float v = Ys[c * 68 + j];
            s += v; s2 += v * v;
        }
        sred[part * 64 + j] = s;
        s2red[part * 64 + j] = s2;
    }
    __syncthreads();
    if (t < 64) {
        float a = 0.f, bq = 0.f;
#pragma unroll
        for (int pp = 0; pp < 4; pp++) { a += sred[pp * 64 + t]; bq += s2red[pp * 64 + t]; }
        float m = a * (1.f / 128.f);
        float var = bq * (1.f / 128.f) - m * m;
        smean[t] = m;
        srstd[t] = rsqrtf(var + 1e-6f);
    }
    __syncthreads();
    {
        const float m = smean[j], r = srstd[j];
        for (int c = part * 32; c < part * 32 + 32; c++) {
            float v = Ys[c * 68 + j];
            Ys[c * 68 + j] = (v - m) * r * lng[c] + lnb[c];
        }
    }
    __syncthreads();

    const int tx = t & 15, ty = t >> 4;
    float acc[4][8];
#pragma unroll
    for (int i = 0; i < 4; i++)
#pragma unroll
        for (int jo = 0; jo < 8; jo++) acc[i][jo] = 0.f;

#pragma unroll 4
    for (int c = 0; c < 128; ++c) {
        float4 xa = *(const float4*)&Ys[c * 68 + tx * 4];
        float4 w0 = *(const float4*)&Ws[c * 132 + ty * 8];
        float4 w1 = *(const float4*)&Ws[c * 132 + ty * 8 + 4];
        float xv[4] = {xa.x, xa.y, xa.z, xa.w};
        float wv[8] = {w0.x, w0.y, w0.z, w0.w, w1.x, w1.y, w1.z, w1.w};
#pragma unroll
        for (int i = 0; i < 4; i++)
#pragma unroll
            for (int jo = 0; jo < 8; jo++) acc[i][jo] += xv[i] * wv[jo];
    }
#pragma unroll
    for (int jo = 0; jo < 8; jo++) {
        int o = ty * 8 + jo;
        float4 v = make_float4(acc[0][jo], acc[1][jo], acc[2][jo], acc[3][jo]);
        *(float4*)&out[(b * Cn + o) * HW + hw0 + tx * 4] = v;
    }
}

// =====================================================================
extern "C" void kernel_launch(void* const* d_in, const int* in_sizes, int n_in,
                              void* d_out, int out_size) {
    const float* x      = (const float*)d_in[0];
    const float* inw    = (const float*)d_in[1];
    const float* c2w    = (const float*)d_in[2];
    const float* c2b    = (const float*)d_in[3];
    const float* dww    = (const float*)d_in[4];
    const float* dwb    = (const float*)d_in[5];
    const float* dlng   = (const float*)d_in[6];
    const float* dlnb   = (const float*)d_in[7];
    const float* offw   = (const float*)d_in[8];
    const float* offb   = (const float*)d_in[9];
    const float* xpw    = (const float*)d_in[10];
    const float* dtw    = (const float*)d_in[11];
    const float* dtb    = (const float*)d_in[12];
    const float* alog   = (const float*)d_in[13];
    const float* Ds     = (const float*)d_in[14];
    const float* olng   = (const float*)d_in[15];
    const float* olnb   = (const float*)d_in[16];
    const float* outw   = (const float*)d_in[17];
    float* out = (float*)d_out;

    const int smem_in  = (128 * 132 + 128 * 68) * 4;
    const int smem_out = (128 * 132 + 128 * 68 + 256 + 256 + 64 + 64) * 4;
    cudaFuncSetAttribute(k_in_proj,  cudaFuncAttributeMaxDynamicSharedMemorySize, smem_in);
    cudaFuncSetAttribute(k_out_proj, cudaFuncAttributeMaxDynamicSharedMemorySize, smem_out);

    k_in_proj<<<P / 64, 256, smem_in>>>(x, inw);
    k_dwsilu<<<P / 2, 256>>>(c2w, c2b);
    k_dw2_off<<<P, 128>>>(dww, dwb, dlng, dlnb, offw, offb);
    k_dcn<<<P, 128>>>();
    k_xdbl<<<P / 32, 320>>>(xpw);
    k_scan1<<<dim3(NCH, Bz), 128>>>(dtw, dtb, alog);
    k_scan2<<<Bz, 128>>>();
    k_scan3<<<dim3(NCH, Bz), 128>>>(dtw, dtb, alog, Ds);
    k_out_proj<<<P / 64, 256, smem_out>>>(outw, olng, olnb, out);
}